// round 15
// baseline (speedup 1.0000x reference)
#include <cuda_runtime.h>
#include <cuda_fp16.h>
#include <math.h>

// Problem constants
#define Nn 256   // nodes
#define Tt 256   // features
#define Bb 64    // batch
#define Dd 64    // emb dim
#define Kk 16    // top-k neighbors

// Scratch (static device globals: no allocation)
__device__ float g_cos[Nn * Nn];     // cosine similarity matrix, 256KB
__device__ int   g_nbr[Nn * Kk];
__device__ float g_coef[Nn * Kk];
// fp16 W^T ([N=256 rows][K], k-chunks of 64), swizzled tiles (32KB/chunk)
__device__ __align__(16) __half g_bh[Tt * Tt];        // 128 KB

__device__ __forceinline__ unsigned swz(unsigned o) { return o ^ ((o >> 3) & 0x70); }

__device__ __forceinline__ unsigned smem_u32(const void* p) {
    unsigned a;
    asm("{ .reg .u64 t; cvta.to.shared.u64 t, %1; cvt.u32.u64 %0, t; }" : "=r"(a) : "l"(p));
    return a;
}

// ---------------------------------------------------------------------------
// Kernel 1: cos matrix (blocks 0..31, 8 rows each; emb loaded ONCE per block)
//           + W prep (blocks 32..47).
// ---------------------------------------------------------------------------
#define ES4_STRIDE 17                         // float4 stride (68 floats; odd -> conflict-free)
#define COS_SMEM  ((Nn * 68 + Nn) * 4)        // es + ssq = 70656 bytes

__global__ __launch_bounds__(256) void cos_kernel(
    const float* __restrict__ emb,
    const float* __restrict__ W)
{
    const int tid = threadIdx.x;

    if (blockIdx.x >= 32) {
        // ---- W prep: 16 blocks x 4096 elements, fp16 swizzled tiles ----
        #pragma unroll
        for (int t = 0; t < 16; t++) {
            int idx = (blockIdx.x - 32) * 4096 + tid + 256 * t;   // 0..65535
            int n = idx & 255;
            int k = idx >> 8;
            __half hi = __float2half_rn(W[k * 256 + n]);
            int kc = k >> 6, cc = k & 63;
            unsigned off = swz((unsigned)(n * 128 + cc * 2));
            *(__half*)((char*)g_bh + (size_t)kc * 32768 + off) = hi;
        }
        return;
    }

    extern __shared__ float smf[];
    float4* es4 = (float4*)smf;          // [256][17] float4  (= [256][68] floats)
    float*  ssq = smf + Nn * 68;         // [256]

    const int i0 = blockIdx.x * 8;

    // coalesced load emb -> padded smem rows
    #pragma unroll
    for (int t = 0; t < 16; t++) {
        int lin4 = tid + 256 * t;        // float4 index: j*16 + d4
        int j = lin4 >> 4, d4 = lin4 & 15;
        es4[j * ES4_STRIDE + d4] = ((const float4*)emb)[lin4];
    }
    __syncthreads();

    // per-thread: dot(emb[i0+r], emb[tid]) for r=0..7, and ||emb[tid]||^2
    float dot[8];
    #pragma unroll
    for (int r = 0; r < 8; r++) dot[r] = 0.f;
    float ss = 0.f;
    #pragma unroll
    for (int d4 = 0; d4 < 16; d4++) {
        float4 a = es4[tid * ES4_STRIDE + d4];   // conflict-free (odd stride)
        ss += a.x * a.x; ss += a.y * a.y; ss += a.z * a.z; ss += a.w * a.w;
        #pragma unroll
        for (int r = 0; r < 8; r++) {
            float4 w = es4[(i0 + r) * ES4_STRIDE + d4];   // broadcast
            dot[r] += a.x * w.x; dot[r] += a.y * w.y;
            dot[r] += a.z * w.z; dot[r] += a.w * w.w;
        }
    }
    ssq[tid] = ss;
    __syncthreads();

    const float nj = sqrtf(ss);
    #pragma unroll
    for (int r = 0; r < 8; r++)
        g_cos[(i0 + r) * Nn + tid] = dot[r] / (sqrtf(ssq[i0 + r]) * nj);
}

// ---------------------------------------------------------------------------
// Kernel 2: rank + gates. One block per destination row i (256-way parallel).
// rank(j) = #{t: cos>cos_j} + #{t<j: cos==cos_j}; selected iff rank<16;
// rank == top-k position (matches lax.top_k incl. tie-break).
// ---------------------------------------------------------------------------
__global__ __launch_bounds__(256) void rank_kernel(
    const float* __restrict__ logits,
    const float* __restrict__ gu)
{
    __shared__ float sval[Nn];
    const int i   = blockIdx.x;
    const int tid = threadIdx.x;

    sval[tid] = g_cos[i * Nn + tid];
    __syncthreads();
    const float v = sval[tid];

    int cnt = 0;
    const float4* sv4 = (const float4*)sval;
    #pragma unroll 8
    for (int t4 = 0; t4 < 64; t4++) {
        float4 w = sv4[t4];            // broadcast
        int t = t4 * 4;
        cnt += (w.x > v) || (w.x == v && (t + 0) < tid);
        cnt += (w.y > v) || (w.y == v && (t + 1) < tid);
        cnt += (w.z > v) || (w.z == v && (t + 2) < tid);
        cnt += (w.w > v) || (w.w == v && (t + 3) < tid);
    }

    if (cnt < Kk) {
        const int j = tid;
        const int e = i * Nn + j;
        float l0 = logits[2 * e], l1 = logits[2 * e + 1];
        float u0 = gu[2 * e],     u1 = gu[2 * e + 1];
        float a0 = l0 - logf(-logf(u0));
        float a1 = l1 - logf(-logf(u1));
        float m  = fmaxf(a0, a1);
        float e0 = expf(a0 - m), e1 = expf(a1 - m);
        float s0 = e0 / (e0 + e1);
        float hard = (a0 >= a1) ? 1.0f : 0.0f;
        float gate = (hard + s0) - s0;          // straight-through fp order
        g_nbr[i * Kk + cnt]  = j;
        g_coef[i * Kk + cnt] = 0.0625f * gate;  // ew == 1/16 exactly (deg==16)
    }
}

// ---------------------------------------------------------------------------
// Kernel 3 (FUSED): per CTA (mt = 0..127: b = mt>>1, node half = mt&1),
// for each k-chunk c: stage x[b,:,c*64..] as fp16 in smem, scalar-gather the
// g tile [128 x 64] into smem (SW128 image), then mma it against W chunk c
// (cp.async double-buffered). g never touches gmem. 512 threads, 16 warps,
// warp tile 64x32 over the 128x256 output. Epilogue adds bias.
//
// SMEM map: [0,32K) xs fp16 [256 j][32 half2]; [32K,96K) g image (4x16KB);
// [96K,104K) sn; [104K,112K) sc; [112K,176K) Bbuf 2x32KB.
// ---------------------------------------------------------------------------
#define FS_XS   0
#define FS_G    32768
#define FS_SN   98304
#define FS_SC   106496
#define FS_B    114688
#define FSMEM   (FS_B + 2 * 32768)   // 180224

#define LDSM4(r, addr) \
    asm volatile("ldmatrix.sync.aligned.m8n8.x4.shared.b16 {%0,%1,%2,%3}, [%4];" \
        : "=r"((r)[0]), "=r"((r)[1]), "=r"((r)[2]), "=r"((r)[3]) : "r"(addr))

#define MMA16816(d, a, b0, b1) \
    asm volatile("mma.sync.aligned.m16n8k16.row.col.f32.f16.f16.f32 " \
        "{%0,%1,%2,%3}, {%4,%5,%6,%7}, {%8,%9}, {%0,%1,%2,%3};" \
        : "+f"((d)[0]), "+f"((d)[1]), "+f"((d)[2]), "+f"((d)[3]) \
        : "r"((a)[0]), "r"((a)[1]), "r"((a)[2]), "r"((a)[3]), "r"(b0), "r"(b1))

__global__ __launch_bounds__(512, 1) void fused_kernel(
    const float* __restrict__ x,
    const float* __restrict__ bias,
    float* __restrict__ out)
{
    extern __shared__ __align__(16) unsigned char sm[];
    const unsigned sb = smem_u32(sm);
    const int tid  = threadIdx.x;
    const int lane = tid & 31;
    const int wid  = tid >> 5;
    const int mt   = blockIdx.x;          // 0..127
    const int b    = mt >> 1;
    const int i0   = (mt & 1) * 128;      // node-row base of this tile

    __half2* xs = (__half2*)(sm + FS_XS);   // [256][32] (rows 128B)
    int*    sn  = (int*)(sm + FS_SN);       // [128][16]
    float*  sc  = (float*)(sm + FS_SC);     // [128][16]

    // tables for this tile's 128 destination rows
    ((int4*)sn)[tid]   = ((const int4*)(g_nbr  + i0 * Kk))[tid];
    ((float4*)sc)[tid] = ((const float4*)(g_coef + i0 * Kk))[tid];

    // prefetch W chunks 0,1 (pre-swizzled 32KB tile images)
    #pragma unroll
    for (int st = 0; st < 2; st++) {
        const char* s = (const char*)g_bh + (size_t)st * 32768;
        const unsigned dd = sb + FS_B + st * 32768;
        #pragma unroll
        for (int t = 0; t < 4; t++) {
            const unsigned o = (unsigned)(tid + 512 * t) * 16u;
            asm volatile("cp.async.cg.shared.global [%0], [%1], 16;"
                         :: "r"(dd + o), "l"(s + o));
        }
        asm volatile("cp.async.commit_group;" ::: "memory");
    }

    const float* xb = x + (size_t)b * Nn * Tt;

    // phase-2 lane offsets (pre-swizzle)
    const unsigned colSel = (lane & 16) ? 16u : 0u;
    const int wm = wid >> 3;     // 0..1  (64 rows)
    const int wn = wid & 7;      // 0..7  (32 cols)
    unsigned aoff[4], boff[2];
    #pragma unroll
    for (int mf = 0; mf < 4; mf++)
        aoff[mf] = (unsigned)((wm * 64 + mf * 16 + (lane & 15)) * 128) + colSel;
    #pragma unroll
    for (int g = 0; g < 2; g++)
        boff[g] = (unsigned)((wn * 32 + g * 16 + (lane & 15)) * 128) + colSel;

    float acc[4][4][4];
    #pragma unroll
    for (int mf = 0; mf < 4; mf++)
        #pragma unroll
        for (int nf = 0; nf < 4; nf++)
            #pragma unroll
            for (int e = 0; e < 4; e++) acc[mf][nf][e] = 0.f;

    __syncthreads();   // tables ready

    #pragma unroll 1
    for (int c = 0; c < 4; c++) {
        // ---- load x chunk c -> fp16 xs (4 x 16B blocks per thread) ----
        #pragma unroll
        for (int q = 0; q < 4; q++) {
            int d = tid + 512 * q;          // 0..2047
            int j = d >> 3, t8 = d & 7;
            const float4* s4 = (const float4*)(xb + j * Tt + c * 64 + t8 * 8);
            float4 v0 = s4[0], v1 = s4[1];
            __half2 h0 = __floats2half2_rn(v0.x, v0.y);
            __half2 h1 = __floats2half2_rn(v0.z, v0.w);
            __half2 h2 = __floats2half2_rn(v1.x, v1.y);
            __half2 h3 = __floats2half2_rn(v1.z, v1.w);
            uint4 u;
            u.x = *(unsigned*)&h0; u.y = *(unsigned*)&h1;
            u.z = *(unsigned*)&h2; u.w = *(unsigned*)&h3;
            *(uint4*)(sm + FS_XS + j * 128 + t8 * 16) = u;
        }
        __syncthreads();   // xs ready

        // ---- gather: warp wid handles rows wid*8 .. wid*8+7 ----
        #pragma unroll 2
        for (int rr = 0; rr < 8; rr++) {
            int i = wid * 8 + rr;           // local row 0..127
            float a0 = 0.f, a1 = 0.f;
            #pragma unroll
            for (int k = 0; k < Kk; k++) {
                int   j  = sn[i * Kk + k];      // warp-uniform broadcast
                float cf = sc[i * Kk + k];
                float2 f = __half22float2(xs[j * 32 + lane]);
                a0 += cf * f.x;
                a1 += cf * f.y;
            }
            *(__half2*)(sm + FS_G + c * 16384 + swz((unsigned)(i * 128 + lane * 4))) =
                __floats2half2_rn(a0, a1);
        }

        // ---- W chunk c must be resident ----
        if (c < 3) asm volatile("cp.async.wait_group 1;" ::: "memory");
        else       asm volatile("cp.async.wait_group 0;" ::: "memory");
        __syncthreads();   // g tile + B chunk ready

        // ---- mma chunk c ----
        const unsigned gbase = sb + FS_G + (unsigned)c * 16384;
        const unsigned bbase = sb + FS_B + (unsigned)(c & 1) * 32768;
        #pragma unroll
        for (int ks = 0; ks < 4; ks++) {
            unsigned a_h[4][4], b_h[2][4];
            #pragma unroll
            for (int mf = 0; mf < 4; mf++)
                LDSM4(a_h[mf], gbase + swz(aoff[mf] + ks * 32));
            #pragma unroll
            for (int g = 0; g < 2; g++)
                LDSM4(b_h[g], bbase + swz(boff[g] + ks * 32));
            #pragma unroll
            for (int mf = 0; mf < 4; mf++) {
                #pragma unroll
                for (int nf = 0; nf < 4; nf++) {
                    const int g = nf >> 1, p = nf & 1;
                    MMA16816(acc[mf][nf], a_h[mf], b_h[g][p], b_h[g][2 + p]);
                }
            }
        }

        // refill the just-consumed B buffer with chunk c+2 (post-mma barrier)
        if (c < 2) {
            __syncthreads();
            const char* s = (const char*)g_bh + (size_t)(c + 2) * 32768;
            const unsigned dd = sb + FS_B + (unsigned)(c & 1) * 32768;
            #pragma unroll
            for (int t = 0; t < 4; t++) {
                const unsigned o = (unsigned)(tid + 512 * t) * 16u;
                asm volatile("cp.async.cg.shared.global [%0], [%1], 16;"
                             :: "r"(dd + o), "l"(s + o));
            }
            asm volatile("cp.async.commit_group;" ::: "memory");
        } else {
            __syncthreads();   // xs overwrite hazard for next iteration
        }
    }

    // ---- epilogue: bias + store ----
    const int mbase = mt * 128 + wm * 64;
    const int nbase = wn * 32;
    #pragma unroll
    for (int mf = 0; mf < 4; mf++) {
        const int m = mbase + mf * 16 + (lane >> 2);
        #pragma unroll
        for (int nf = 0; nf < 4; nf++) {
            const int n = nbase + nf * 8 + (lane & 3) * 2;
            const float b0 = bias[n], b1 = bias[n + 1];
            float2 v0 = make_float2(acc[mf][nf][0] + b0, acc[mf][nf][1] + b1);
            float2 v1 = make_float2(acc[mf][nf][2] + b0, acc[mf][nf][3] + b1);
            *(float2*)&out[(size_t)m * 256 + n]       = v0;
            *(float2*)&out[(size_t)(m + 8) * 256 + n] = v1;
        }
    }
}

// ---------------------------------------------------------------------------
extern "C" void kernel_launch(void* const* d_in, const int* in_sizes, int n_in,
                              void* d_out, int out_size)
{
    const float* x      = (const float*)d_in[0];   // [64,256,256]
    const float* emb    = (const float*)d_in[1];   // [256,64]
    const float* W      = (const float*)d_in[2];   // [256,256]
    const float* bias   = (const float*)d_in[3];   // [256]
    const float* logits = (const float*)d_in[4];   // [65536,2]
    const float* gu     = (const float*)d_in[5];   // [65536,2]
    float* out = (float*)d_out;                    // [64,256,256]

    cudaFuncSetAttribute(cos_kernel,   cudaFuncAttributeMaxDynamicSharedMemorySize, COS_SMEM);
    cudaFuncSetAttribute(fused_kernel, cudaFuncAttributeMaxDynamicSharedMemorySize, FSMEM);

    cos_kernel<<<48, 256, COS_SMEM>>>(emb, W);
    rank_kernel<<<Nn, 256>>>(logits, gu);
    fused_kernel<<<128, 512, FSMEM>>>(x, bias, out);
}

// round 16
// speedup vs baseline: 1.0031x; 1.0031x over previous
#include <cuda_runtime.h>
#include <cuda_fp16.h>
#include <math.h>

// Problem constants
#define Nn 256   // nodes
#define Tt 256   // features
#define Bb 64    // batch
#define Dd 64    // emb dim
#define Kk 16    // top-k neighbors

// Scratch (static device globals: no allocation)
__device__ float g_cos[Nn * Nn];     // cosine similarity matrix, 256KB
__device__ int   g_nbr[Nn * Kk];
__device__ float g_coef[Nn * Kk];
// fp16 (rounded) g = A@x, pre-swizzled SW128 tile images:
// tile index = (mtile 0..127, kchunk 0..3); each tile 128 rows x 64 cols fp16 = 16KB
__device__ __align__(16) __half g_ah[Bb * Nn * Tt];   // 8 MB
// fp16 W^T ([N=256 rows][K], k-chunks of 64), swizzled tiles (32KB/chunk)
__device__ __align__(16) __half g_bh[Tt * Tt];        // 128 KB

__device__ __forceinline__ unsigned swz(unsigned o) { return o ^ ((o >> 3) & 0x70); }

__device__ __forceinline__ unsigned smem_u32(const void* p) {
    unsigned a;
    asm("{ .reg .u64 t; cvta.to.shared.u64 t, %1; cvt.u32.u64 %0, t; }" : "=r"(a) : "l"(p));
    return a;
}

// ---------------------------------------------------------------------------
// Kernel 1: cos matrix (blocks 0..127, TWO rows each; emb staged once per
// block -> short 3-load dependency chain per iter, 128 SMs busy)
//           + W prep (blocks 128..143).
// ---------------------------------------------------------------------------
#define ES4_STRIDE 17                         // float4 stride (68 floats; odd -> conflict-free)
#define COS_SMEM  ((Nn * 68 + Nn) * 4)        // es + ssq = 70656 bytes

__global__ __launch_bounds__(256) void cos_kernel(
    const float* __restrict__ emb,
    const float* __restrict__ W)
{
    const int tid = threadIdx.x;

    if (blockIdx.x >= 128) {
        // ---- W prep: 16 blocks x 4096 elements, fp16 swizzled tiles ----
        #pragma unroll
        for (int t = 0; t < 16; t++) {
            int idx = (blockIdx.x - 128) * 4096 + tid + 256 * t;   // 0..65535
            int n = idx & 255;
            int k = idx >> 8;
            __half hi = __float2half_rn(W[k * 256 + n]);
            int kc = k >> 6, cc = k & 63;
            unsigned off = swz((unsigned)(n * 128 + cc * 2));
            *(__half*)((char*)g_bh + (size_t)kc * 32768 + off) = hi;
        }
        return;
    }

    extern __shared__ float smf[];
    float4* es4 = (float4*)smf;          // [256][17] float4  (= [256][68] floats)
    float*  ssq = smf + Nn * 68;         // [256]

    const int i0 = blockIdx.x * 2;

    // coalesced load emb -> padded smem rows
    #pragma unroll
    for (int t = 0; t < 16; t++) {
        int lin4 = tid + 256 * t;        // float4 index: j*16 + d4
        int j = lin4 >> 4, d4 = lin4 & 15;
        es4[j * ES4_STRIDE + d4] = ((const float4*)emb)[lin4];
    }
    __syncthreads();

    // per-thread: dot(emb[i0+r], emb[tid]) for r=0..1, and ||emb[tid]||^2
    float dot0 = 0.f, dot1 = 0.f, ss = 0.f;
    #pragma unroll
    for (int d4 = 0; d4 < 16; d4++) {
        float4 a  = es4[tid * ES4_STRIDE + d4];        // conflict-free (odd stride)
        float4 w0 = es4[i0 * ES4_STRIDE + d4];         // broadcast
        float4 w1 = es4[(i0 + 1) * ES4_STRIDE + d4];   // broadcast
        ss   += a.x * a.x + a.y * a.y + a.z * a.z + a.w * a.w;
        dot0 += a.x * w0.x + a.y * w0.y + a.z * w0.z + a.w * w0.w;
        dot1 += a.x * w1.x + a.y * w1.y + a.z * w1.z + a.w * w1.w;
    }
    ssq[tid] = ss;
    __syncthreads();

    const float nj = sqrtf(ss);
    g_cos[i0 * Nn + tid]       = dot0 / (sqrtf(ssq[i0]) * nj);
    g_cos[(i0 + 1) * Nn + tid] = dot1 / (sqrtf(ssq[i0 + 1]) * nj);
}

// ---------------------------------------------------------------------------
// Kernel 2: rank + gates. One block per destination row i (256-way parallel).
// rank(j) = #{t: cos>cos_j} + #{t<j: cos==cos_j}; selected iff rank<16;
// rank == top-k position (matches lax.top_k incl. tie-break).
// ---------------------------------------------------------------------------
__global__ __launch_bounds__(256) void rank_kernel(
    const float* __restrict__ logits,
    const float* __restrict__ gu)
{
    __shared__ float sval[Nn];
    const int i   = blockIdx.x;
    const int tid = threadIdx.x;

    sval[tid] = g_cos[i * Nn + tid];
    __syncthreads();
    const float v = sval[tid];

    int cnt = 0;
    const float4* sv4 = (const float4*)sval;
    #pragma unroll 8
    for (int t4 = 0; t4 < 64; t4++) {
        float4 w = sv4[t4];            // broadcast
        int t = t4 * 4;
        cnt += (w.x > v) || (w.x == v && (t + 0) < tid);
        cnt += (w.y > v) || (w.y == v && (t + 1) < tid);
        cnt += (w.z > v) || (w.z == v && (t + 2) < tid);
        cnt += (w.w > v) || (w.w == v && (t + 3) < tid);
    }

    if (cnt < Kk) {
        const int j = tid;
        const int e = i * Nn + j;
        float l0 = logits[2 * e], l1 = logits[2 * e + 1];
        float u0 = gu[2 * e],     u1 = gu[2 * e + 1];
        float a0 = l0 - logf(-logf(u0));
        float a1 = l1 - logf(-logf(u1));
        float m  = fmaxf(a0, a1);
        float e0 = expf(a0 - m), e1 = expf(a1 - m);
        float s0 = e0 / (e0 + e1);
        float hard = (a0 >= a1) ? 1.0f : 0.0f;
        float gate = (hard + s0) - s0;          // straight-through fp order
        g_nbr[i * Kk + cnt]  = j;
        g_coef[i * Kk + cnt] = 0.0625f * gate;  // ew == 1/16 exactly (deg==16)
    }
}

// ---------------------------------------------------------------------------
// Kernel 3: gather  g[b,i,:] = sum_k coef[i,k] * x[b, nbr[i,k], :]
// Grid (4 k-chunks, B). x chunk staged in smem as HALF2 (32KB: halves the
// crossbar traffic, which is the kernel's floor) + nbr/coef tables (32KB).
// Accumulation in fp32; half2 store into the pre-swizzled SW128 tile layout.
// ---------------------------------------------------------------------------
#define GATHER_SMEM (Nn * 32 * 4 + Nn * Kk * 4 * 2)   // 32KB xs + 16KB sn + 16KB sc = 64KB

__global__ __launch_bounds__(256) void gather_kernel(const float* __restrict__ x)
{
    extern __shared__ __align__(16) unsigned char smraw[];
    unsigned* xs = (unsigned*)smraw;               // [Nn][32] half2-as-u32 (64 cols)
    int*   sn = (int*)(smraw + Nn * 32 * 4);       // [Nn][16]
    float* sc = (float*)(sn + Nn * Kk);            // [Nn][16]

    const int kc  = blockIdx.x;     // 0..3
    const int b   = blockIdx.y;
    const int tid = threadIdx.x;
    const int wid = tid >> 5;
    const int lane = tid & 31;

    const float* xb = x + (size_t)b * Nn * Tt + kc * 64;
    // 256 rows x 16 float4 = 4096 float4; convert to half2 pairs, 8B stores
    #pragma unroll
    for (int t = 0; t < 16; t++) {
        int idx = tid + 256 * t;
        int r = idx >> 4, c4 = idx & 15;
        float4 v = *(const float4*)&xb[r * Tt + c4 * 4];
        __half2 h0 = __floats2half2_rn(v.x, v.y);
        __half2 h1 = __floats2half2_rn(v.z, v.w);
        uint2 u;
        u.x = *(unsigned*)&h0;
        u.y = *(unsigned*)&h1;
        *(uint2*)&xs[r * 32 + c4 * 2] = u;
    }
    #pragma unroll
    for (int t = 0; t < 4; t++) {
        ((int4*)sn)[tid + 256 * t]   = ((const int4*)g_nbr)[tid + 256 * t];
        ((float4*)sc)[tid + 256 * t] = ((const float4*)g_coef)[tid + 256 * t];
    }
    __syncthreads();

    #pragma unroll 4
    for (int it = 0; it < 32; it++) {
        int i = wid + (it << 3);
        float a0 = 0.f, a1 = 0.f;
        #pragma unroll
        for (int k = 0; k < Kk; k++) {
            int   j  = sn[i * Kk + k];     // warp-uniform broadcast
            float cf = sc[i * Kk + k];
            unsigned uv = xs[j * 32 + lane];   // 4B/lane, conflict-free
            __half2 hv = *(__half2*)&uv;
            float2 f = __half22float2(hv);
            a0 += cf * f.x;
            a1 += cf * f.y;
        }
        int m  = b * Nn + i;
        int mt = m >> 7;
        int r  = m & 127;
        unsigned off = swz((unsigned)(r * 128 + lane * 4));
        *(__half2*)((char*)g_ah + (size_t)(mt * 4 + kc) * 16384 + off) =
            __floats2half2_rn(a0, a1);
    }
}

// ---------------------------------------------------------------------------
// Kernel 4: out = g @ W + bias via mma.sync, single fp16 product, fp32 accum.
// EXACT R10 measured-best config: BM=128, BN=128, BK=64 per stage; 8 warps,
// warp tile 64x32; cp.async 2-stage double buffer (32KB/stage).
// ---------------------------------------------------------------------------
#define STAGEB 32768
#define GSMEM  (2 * STAGEB)

#define LDSM4(r, addr) \
    asm volatile("ldmatrix.sync.aligned.m8n8.x4.shared.b16 {%0,%1,%2,%3}, [%4];" \
        : "=r"((r)[0]), "=r"((r)[1]), "=r"((r)[2]), "=r"((r)[3]) : "r"(addr))

#define MMA16816(d, a, b0, b1) \
    asm volatile("mma.sync.aligned.m16n8k16.row.col.f32.f16.f16.f32 " \
        "{%0,%1,%2,%3}, {%4,%5,%6,%7}, {%8,%9}, {%0,%1,%2,%3};" \
        : "+f"((d)[0]), "+f"((d)[1]), "+f"((d)[2]), "+f"((d)[3]) \
        : "r"((a)[0]), "r"((a)[1]), "r"((a)[2]), "r"((a)[3]), "r"(b0), "r"(b1))

__global__ __launch_bounds__(256, 2) void gemm_kernel(
    const float* __restrict__ bias, float* __restrict__ out)
{
    extern __shared__ unsigned char sm[];
    const unsigned sb = smem_u32(sm);
    const int tid  = threadIdx.x;
    const int lane = tid & 31;
    const int wid  = tid >> 5;
    const int mt   = blockIdx.x;   // 0..127
    const int nt   = blockIdx.y;   // 0..1
    const int wm   = wid >> 2;     // 0..1 (64 rows each)
    const int wn   = wid & 3;      // 0..3 (32 cols each)

    const char* aH = (const char*)g_ah + (size_t)mt * 65536;
    const char* bH = (const char*)g_bh + (size_t)nt * 16384;

    // stage fill: pure linear 16B copies (tiles are pre-swizzled in gmem)
    auto load_stage = [&](int st, int c) {
        const unsigned d = sb + st * STAGEB;
        const char* srcs[2] = { aH + c * 16384, bH + c * 32768 };
        #pragma unroll
        for (int rgn = 0; rgn < 2; rgn++) {
            const char* s = srcs[rgn];
            const unsigned dd = d + rgn * 16384;
            #pragma unroll
            for (int t = 0; t < 4; t++) {
                const unsigned o = (unsigned)(tid + 256 * t) * 16u;
                asm volatile("cp.async.cg.shared.global [%0], [%1], 16;"
                             :: "r"(dd + o), "l"(s + o));
            }
        }
        asm volatile("cp.async.commit_group;" ::: "memory");
    };

    // per-lane ldmatrix byte offsets (pre-swizzle)
    const unsigned colSel = (lane & 16) ? 16u : 0u;
    unsigned aoff[4], boff[2];
    #pragma unroll
    for (int mf = 0; mf < 4; mf++)
        aoff[mf] = (unsigned)((wm * 64 + mf * 16 + (lane & 15)) * 128) + colSel;
    #pragma unroll
    for (int g = 0; g < 2; g++)
        boff[g] = (unsigned)((wn * 32 + g * 16 + (lane & 15)) * 128) + colSel;

    float acc[4][4][4];
    #pragma unroll
    for (int mf = 0; mf < 4; mf++)
        #pragma unroll
        for (int nf = 0; nf < 4; nf++)
            #pragma unroll
            for (int e = 0; e < 4; e++) acc[mf][nf][e] = 0.f;

    load_stage(0, 0);

    #pragma unroll 1
    for (int c = 0; c < 4; c++) {
        if (c < 3) {
            load_stage((c + 1) & 1, c + 1);
            asm volatile("cp.async.wait_group 1;" ::: "memory");
        } else {
            asm volatile("cp.async.wait_group 0;" ::: "memory");
        }
        __syncthreads();

        const unsigned base = sb + (c & 1) * STAGEB;
        #pragma unroll
        for (int ks = 0; ks < 4; ks++) {
            unsigned a_h[4][4], b_h[2][4];
            #pragma unroll
            for (int mf = 0; mf < 4; mf++)
                LDSM4(a_h[mf], base + swz(aoff[mf] + ks * 32));
            #pragma unroll
            for (int g = 0; g < 2; g++)
                LDSM4(b_h[g], base + 16384 + swz(boff[g] + ks * 32));
            #pragma unroll
            for (int mf = 0; mf < 4; mf++) {
                #pragma unroll
                for (int nf = 0; nf < 4; nf++) {
                    const int g = nf >> 1, p = nf & 1;
                    MMA16816(acc[mf][nf], a_h[mf], b_h[g][p], b_h[g][2 + p]);
                }
            }
        }
        __syncthreads();
    }

    // epilogue
    const int mbase = mt * 128 + wm * 64;
    const int nbase = nt * 128 + wn * 32;
    #pragma unroll
    for (int mf = 0; mf < 4; mf++) {
        const int m = mbase + mf * 16 + (lane >> 2);
        #pragma unroll
        for (int nf = 0; nf < 4; nf++) {
            const int n = nbase + nf * 8 + (lane & 3) * 2;
            const float b0 = bias[n], b1 = bias[n + 1];
            float2 v0 = make_float2(acc[mf][nf][0] + b0, acc[mf][nf][1] + b1);
            float2 v1 = make_float2(acc[mf][nf][2] + b0, acc[mf][nf][3] + b1);
            *(float2*)&out[(size_t)m * 256 + n]       = v0;
            *(float2*)&out[(size_t)(m + 8) * 256 + n] = v1;
        }
    }
}

// ---------------------------------------------------------------------------
extern "C" void kernel_launch(void* const* d_in, const int* in_sizes, int n_in,
                              void* d_out, int out_size)
{
    const float* x      = (const float*)d_in[0];   // [64,256,256]
    const float* emb    = (const float*)d_in[1];   // [256,64]
    const float* W      = (const float*)d_in[2];   // [256,256]
    const float* bias   = (const float*)d_in[3];   // [256]
    const float* logits = (const float*)d_in[4];   // [65536,2]
    const float* gu     = (const float*)d_in[5];   // [65536,2]
    float* out = (float*)d_out;                    // [64,256,256]

    cudaFuncSetAttribute(cos_kernel,    cudaFuncAttributeMaxDynamicSharedMemorySize, COS_SMEM);
    cudaFuncSetAttribute(gather_kernel, cudaFuncAttributeMaxDynamicSharedMemorySize, GATHER_SMEM);
    cudaFuncSetAttribute(gemm_kernel,   cudaFuncAttributeMaxDynamicSharedMemorySize, GSMEM);

    cos_kernel<<<144, 256, COS_SMEM>>>(emb, W);
    rank_kernel<<<Nn, 256>>>(logits, gu);
    gather_kernel<<<dim3(4, Bb), 256, GATHER_SMEM>>>(x);
    gemm_kernel<<<dim3(128, 2), 256, GSMEM>>>(bias, out);
}

// round 17
// speedup vs baseline: 1.0567x; 1.0535x over previous
#include <cuda_runtime.h>
#include <cuda_fp16.h>
#include <math.h>

// Problem constants
#define Nn 256   // nodes
#define Tt 256   // features
#define Bb 64    // batch
#define Dd 64    // emb dim
#define Kk 16    // top-k neighbors

// Scratch (static device globals: no allocation)
__device__ int   g_nbr[Nn * Kk];
__device__ float g_coef[Nn * Kk];
// fp16 (rounded) g = A@x, pre-swizzled SW128 tile images:
// tile index = (mtile 0..127, kchunk 0..3); each tile 128 rows x 64 cols fp16 = 16KB
__device__ __align__(16) __half g_ah[Bb * Nn * Tt];   // 8 MB
// fp16 W^T ([N=256 rows][K], k-chunks of 64), swizzled tiles (32KB/chunk)
__device__ __align__(16) __half g_bh[Tt * Tt];        // 128 KB

__device__ __forceinline__ unsigned swz(unsigned o) { return o ^ ((o >> 3) & 0x70); }

__device__ __forceinline__ unsigned smem_u32(const void* p) {
    unsigned a;
    asm("{ .reg .u64 t; cvta.to.shared.u64 t, %1; cvt.u32.u64 %0, t; }" : "=r"(a) : "l"(p));
    return a;
}

// ---------------------------------------------------------------------------
// Kernel 1: cos + rank + gates, FUSED. Blocks 0..127: TWO full cos rows per
// block (each block holds rows i0, i0+1 across its 256 threads), ranked
// in-smem immediately — no g_cos round-trip, no separate rank launch.
// rank(j) = #{t: cos>cos_j} + #{t<j: cos==cos_j}; selected iff rank<16;
// rank == top-k position (matches lax.top_k incl. tie-break).
// Blocks 128..143: W prep (fp16 swizzled tile images).
// ---------------------------------------------------------------------------
#define ES4_STRIDE 17                              // float4 stride (68 floats; odd -> conflict-free)
#define CR_SMEM  ((Nn * 68 + 3 * Nn) * 4)          // es4 + ssq + srow0 + srow1 = 72704 bytes

__global__ __launch_bounds__(256) void cosrank_kernel(
    const float* __restrict__ emb,
    const float* __restrict__ W,
    const float* __restrict__ logits,
    const float* __restrict__ gu)
{
    const int tid = threadIdx.x;

    if (blockIdx.x >= 128) {
        // ---- W prep: 16 blocks x 4096 elements, fp16 swizzled tiles ----
        #pragma unroll
        for (int t = 0; t < 16; t++) {
            int idx = (blockIdx.x - 128) * 4096 + tid + 256 * t;   // 0..65535
            int n = idx & 255;
            int k = idx >> 8;
            __half hi = __float2half_rn(W[k * 256 + n]);
            int kc = k >> 6, cc = k & 63;
            unsigned off = swz((unsigned)(n * 128 + cc * 2));
            *(__half*)((char*)g_bh + (size_t)kc * 32768 + off) = hi;
        }
        return;
    }

    extern __shared__ float smf[];
    float4* es4   = (float4*)smf;            // [256][17] float4 (= [256][68] floats)
    float*  ssq   = smf + Nn * 68;           // [256]
    float*  srow0 = ssq + Nn;                // [256]
    float*  srow1 = srow0 + Nn;              // [256]

    const int i0 = blockIdx.x * 2;

    // coalesced load emb -> padded smem rows
    #pragma unroll
    for (int t = 0; t < 16; t++) {
        int lin4 = tid + 256 * t;            // float4 index: j*16 + d4
        int j = lin4 >> 4, d4 = lin4 & 15;
        es4[j * ES4_STRIDE + d4] = ((const float4*)emb)[lin4];
    }
    __syncthreads();

    // per-thread: dot(emb[i0+r], emb[tid]) for r=0..1, and ||emb[tid]||^2
    float dot0 = 0.f, dot1 = 0.f, ss = 0.f;
    #pragma unroll
    for (int d4 = 0; d4 < 16; d4++) {
        float4 a  = es4[tid * ES4_STRIDE + d4];        // conflict-free (odd stride)
        float4 w0 = es4[i0 * ES4_STRIDE + d4];         // broadcast
        float4 w1 = es4[(i0 + 1) * ES4_STRIDE + d4];   // broadcast
        ss   += a.x * a.x + a.y * a.y + a.z * a.z + a.w * a.w;
        dot0 += a.x * w0.x + a.y * w0.y + a.z * w0.z + a.w * w0.w;
        dot1 += a.x * w1.x + a.y * w1.y + a.z * w1.z + a.w * w1.w;
    }
    ssq[tid] = ss;
    __syncthreads();

    const float nj = sqrtf(ss);
    const float v0 = dot0 / (sqrtf(ssq[i0]) * nj);       // cos(i0,   tid)
    const float v1 = dot1 / (sqrtf(ssq[i0 + 1]) * nj);   // cos(i0+1, tid)
    srow0[tid] = v0;
    srow1[tid] = v1;
    __syncthreads();

    // rank both rows by counting (float4 broadcast reads)
    int cnt0 = 0, cnt1 = 0;
    const float4* sv0 = (const float4*)srow0;
    const float4* sv1 = (const float4*)srow1;
    #pragma unroll 8
    for (int t4 = 0; t4 < 64; t4++) {
        float4 w0 = sv0[t4];
        float4 w1 = sv1[t4];
        int t = t4 * 4;
        cnt0 += (w0.x > v0) || (w0.x == v0 && (t + 0) < tid);
        cnt0 += (w0.y > v0) || (w0.y == v0 && (t + 1) < tid);
        cnt0 += (w0.z > v0) || (w0.z == v0 && (t + 2) < tid);
        cnt0 += (w0.w > v0) || (w0.w == v0 && (t + 3) < tid);
        cnt1 += (w1.x > v1) || (w1.x == v1 && (t + 0) < tid);
        cnt1 += (w1.y > v1) || (w1.y == v1 && (t + 1) < tid);
        cnt1 += (w1.z > v1) || (w1.z == v1 && (t + 2) < tid);
        cnt1 += (w1.w > v1) || (w1.w == v1 && (t + 3) < tid);
    }

    #pragma unroll
    for (int r = 0; r < 2; r++) {
        const int cnt = r ? cnt1 : cnt0;
        if (cnt < Kk) {
            const int i = i0 + r;
            const int j = tid;
            const int e = i * Nn + j;
            float l0 = logits[2 * e], l1 = logits[2 * e + 1];
            float u0 = gu[2 * e],     u1 = gu[2 * e + 1];
            float a0 = l0 - logf(-logf(u0));
            float a1 = l1 - logf(-logf(u1));
            float m  = fmaxf(a0, a1);
            float e0 = expf(a0 - m), e1 = expf(a1 - m);
            float s0 = e0 / (e0 + e1);
            float hard = (a0 >= a1) ? 1.0f : 0.0f;
            float gate = (hard + s0) - s0;          // straight-through fp order
            g_nbr[i * Kk + cnt]  = j;
            g_coef[i * Kk + cnt] = 0.0625f * gate;  // ew == 1/16 exactly (deg==16)
        }
    }
}

// ---------------------------------------------------------------------------
// Kernel 2: gather  g[b,i,:] = sum_k coef[i,k] * x[b, nbr[i,k], :]
// Grid (4 k-chunks, B). x chunk staged in smem as HALF2 (32KB: halves the
// crossbar traffic, which is the kernel's floor) + nbr/coef tables (32KB).
// Accumulation in fp32; half2 store into the pre-swizzled SW128 tile layout.
// ---------------------------------------------------------------------------
#define GATHER_SMEM (Nn * 32 * 4 + Nn * Kk * 4 * 2)   // 32KB xs + 16KB sn + 16KB sc = 64KB

__global__ __launch_bounds__(256) void gather_kernel(const float* __restrict__ x)
{
    extern __shared__ __align__(16) unsigned char smraw[];
    unsigned* xs = (unsigned*)smraw;               // [Nn][32] half2-as-u32 (64 cols)
    int*   sn = (int*)(smraw + Nn * 32 * 4);       // [Nn][16]
    float* sc = (float*)(sn + Nn * Kk);            // [Nn][16]

    const int kc  = blockIdx.x;     // 0..3
    const int b   = blockIdx.y;
    const int tid = threadIdx.x;
    const int wid = tid >> 5;
    const int lane = tid & 31;

    const float* xb = x + (size_t)b * Nn * Tt + kc * 64;
    // 256 rows x 16 float4 = 4096 float4; convert to half2 pairs, 8B stores
    #pragma unroll
    for (int t = 0; t < 16; t++) {
        int idx = tid + 256 * t;
        int r = idx >> 4, c4 = idx & 15;
        float4 v = *(const float4*)&xb[r * Tt + c4 * 4];
        __half2 h0 = __floats2half2_rn(v.x, v.y);
        __half2 h1 = __floats2half2_rn(v.z, v.w);
        uint2 u;
        u.x = *(unsigned*)&h0;
        u.y = *(unsigned*)&h1;
        *(uint2*)&xs[r * 32 + c4 * 2] = u;
    }
    #pragma unroll
    for (int t = 0; t < 4; t++) {
        ((int4*)sn)[tid + 256 * t]   = ((const int4*)g_nbr)[tid + 256 * t];
        ((float4*)sc)[tid + 256 * t] = ((const float4*)g_coef)[tid + 256 * t];
    }
    __syncthreads();

    #pragma unroll 4
    for (int it = 0; it < 32; it++) {
        int i = wid + (it << 3);
        float a0 = 0.f, a1 = 0.f;
        #pragma unroll
        for (int k = 0; k < Kk; k++) {
            int   j  = sn[i * Kk + k];     // warp-uniform broadcast
            float cf = sc[i * Kk + k];
            unsigned uv = xs[j * 32 + lane];   // 4B/lane, conflict-free
            __half2 hv = *(__half2*)&uv;
            float2 f = __half22float2(hv);
            a0 += cf * f.x;
            a1 += cf * f.y;
        }
        int m  = b * Nn + i;
        int mt = m >> 7;
        int r  = m & 127;
        unsigned off = swz((unsigned)(r * 128 + lane * 4));
        *(__half2*)((char*)g_ah + (size_t)(mt * 4 + kc) * 16384 + off) =
            __floats2half2_rn(a0, a1);
    }
}

// ---------------------------------------------------------------------------
// Kernel 3: out = g @ W + bias via mma.sync, single fp16 product, fp32 accum.
// EXACT R10/R14 measured-best config: BM=128, BN=128, BK=64 per stage; 8
// warps, warp tile 64x32; cp.async 2-stage double buffer (32KB/stage).
// ---------------------------------------------------------------------------
#define STAGEB 32768
#define GSMEM  (2 * STAGEB)

#define LDSM4(r, addr) \
    asm volatile("ldmatrix.sync.aligned.m8n8.x4.shared.b16 {%0,%1,%2,%3}, [%4];" \
        : "=r"((r)[0]), "=r"((r)[1]), "=r"((r)[2]), "=r"((r)[3]) : "r"(addr))

#define MMA16816(d, a, b0, b1) \
    asm volatile("mma.sync.aligned.m16n8k16.row.col.f32.f16.f16.f32 " \
        "{%0,%1,%2,%3}, {%4,%5,%6,%7}, {%8,%9}, {%0,%1,%2,%3};" \
        : "+f"((d)[0]), "+f"((d)[1]), "+f"((d)[2]), "+f"((d)[3]) \
        : "r"((a)[0]), "r"((a)[1]), "r"((a)[2]), "r"((a)[3]), "r"(b0), "r"(b1))

__global__ __launch_bounds__(256, 2) void gemm_kernel(
    const float* __restrict__ bias, float* __restrict__ out)
{
    extern __shared__ unsigned char sm[];
    const unsigned sb = smem_u32(sm);
    const int tid  = threadIdx.x;
    const int lane = tid & 31;
    const int wid  = tid >> 5;
    const int mt   = blockIdx.x;   // 0..127
    const int nt   = blockIdx.y;   // 0..1
    const int wm   = wid >> 2;     // 0..1 (64 rows each)
    const int wn   = wid & 3;      // 0..3 (32 cols each)

    const char* aH = (const char*)g_ah + (size_t)mt * 65536;
    const char* bH = (const char*)g_bh + (size_t)nt * 16384;

    // stage fill: pure linear 16B copies (tiles are pre-swizzled in gmem)
    auto load_stage = [&](int st, int c) {
        const unsigned d = sb + st * STAGEB;
        const char* srcs[2] = { aH + c * 16384, bH + c * 32768 };
        #pragma unroll
        for (int rgn = 0; rgn < 2; rgn++) {
            const char* s = srcs[rgn];
            const unsigned dd = d + rgn * 16384;
            #pragma unroll
            for (int t = 0; t < 4; t++) {
                const unsigned o = (unsigned)(tid + 256 * t) * 16u;
                asm volatile("cp.async.cg.shared.global [%0], [%1], 16;"
                             :: "r"(dd + o), "l"(s + o));
            }
        }
        asm volatile("cp.async.commit_group;" ::: "memory");
    };

    // per-lane ldmatrix byte offsets (pre-swizzle)
    const unsigned colSel = (lane & 16) ? 16u : 0u;
    unsigned aoff[4], boff[2];
    #pragma unroll
    for (int mf = 0; mf < 4; mf++)
        aoff[mf] = (unsigned)((wm * 64 + mf * 16 + (lane & 15)) * 128) + colSel;
    #pragma unroll
    for (int g = 0; g < 2; g++)
        boff[g] = (unsigned)((wn * 32 + g * 16 + (lane & 15)) * 128) + colSel;

    float acc[4][4][4];
    #pragma unroll
    for (int mf = 0; mf < 4; mf++)
        #pragma unroll
        for (int nf = 0; nf < 4; nf++)
            #pragma unroll
            for (int e = 0; e < 4; e++) acc[mf][nf][e] = 0.f;

    load_stage(0, 0);

    #pragma unroll 1
    for (int c = 0; c < 4; c++) {
        if (c < 3) {
            load_stage((c + 1) & 1, c + 1);
            asm volatile("cp.async.wait_group 1;" ::: "memory");
        } else {
            asm volatile("cp.async.wait_group 0;" ::: "memory");
        }
        __syncthreads();

        const unsigned base = sb + (c & 1) * STAGEB;
        #pragma unroll
        for (int ks = 0; ks < 4; ks++) {
            unsigned a_h[4][4], b_h[2][4];
            #pragma unroll
            for (int mf = 0; mf < 4; mf++)
                LDSM4(a_h[mf], base + swz(aoff[mf] + ks * 32));
            #pragma unroll
            for (int g = 0; g < 2; g++)
                LDSM4(b_h[g], base + 16384 + swz(boff[g] + ks * 32));
            #pragma unroll
            for (int mf = 0; mf < 4; mf++) {
                #pragma unroll
                for (int nf = 0; nf < 4; nf++) {
                    const int g = nf >> 1, p = nf & 1;
                    MMA16816(acc[mf][nf], a_h[mf], b_h[g][p], b_h[g][2 + p]);
                }
            }
        }
        __syncthreads();
    }

    // epilogue
    const int mbase = mt * 128 + wm * 64;
    const int nbase = nt * 128 + wn * 32;
    #pragma unroll
    for (int mf = 0; mf < 4; mf++) {
        const int m = mbase + mf * 16 + (lane >> 2);
        #pragma unroll
        for (int nf = 0; nf < 4; nf++) {
            const int n = nbase + nf * 8 + (lane & 3) * 2;
            const float b0 = bias[n], b1 = bias[n + 1];
            float2 v0 = make_float2(acc[mf][nf][0] + b0, acc[mf][nf][1] + b1);
            float2 v1 = make_float2(acc[mf][nf][2] + b0, acc[mf][nf][3] + b1);
            *(float2*)&out[(size_t)m * 256 + n]       = v0;
            *(float2*)&out[(size_t)(m + 8) * 256 + n] = v1;
        }
    }
}

// ---------------------------------------------------------------------------
extern "C" void kernel_launch(void* const* d_in, const int* in_sizes, int n_in,
                              void* d_out, int out_size)
{
    const float* x      = (const float*)d_in[0];   // [64,256,256]
    const float* emb    = (const float*)d_in[1];   // [256,64]
    const float* W      = (const float*)d_in[2];   // [256,256]
    const float* bias   = (const float*)d_in[3];   // [256]
    const float* logits = (const float*)d_in[4];   // [65536,2]
    const float* gu     = (const float*)d_in[5];   // [65536,2]
    float* out = (float*)d_out;                    // [64,256,256]

    cudaFuncSetAttribute(cosrank_kernel, cudaFuncAttributeMaxDynamicSharedMemorySize, CR_SMEM);
    cudaFuncSetAttribute(gather_kernel,  cudaFuncAttributeMaxDynamicSharedMemorySize, GATHER_SMEM);
    cudaFuncSetAttribute(gemm_kernel,    cudaFuncAttributeMaxDynamicSharedMemorySize, GSMEM);

    cosrank_kernel<<<144, 256, CR_SMEM>>>(emb, W, logits, gu);
    gather_kernel<<<dim3(4, Bb), 256, GATHER_SMEM>>>(x);
    gemm_kernel<<<dim3(128, 2), 256, GSMEM>>>(bias, out);
}